// round 7
// baseline (speedup 1.0000x reference)
#include <cuda_runtime.h>

// ---------------------------------------------------------------------------
// RgbNet, R7: single fused kernel.
//  Phase W: transpose W1/W2/W3 into smem via padded staging (conflict-free).
//  Phase E: hash-grid encode, thread per (level, col), 5 samples w/ corner
//           cache -> feat[120][64] in smem (no global roundtrip).
//  Phase M: MLP; 8 warps, warp = 8 outputs x 64 cols (lane owns col pair).
//  Grid = 296 blocks x 56 rays: 2 blocks on every SM, one balanced wave.
// ---------------------------------------------------------------------------

namespace {
constexpr int NRAYS   = 16384;
constexpr int NSAMP   = 300;
constexpr unsigned HSIZE = 1u << 19;
constexpr unsigned HMASK = HSIZE - 1u;

constexpr int THREADS = 256;       // 8 warps
constexpr int RPB     = 56;        // rays per block (cols 56..63 redundant)
constexpr int BLOCKS  = 296;       // 2 per SM on 148 SMs, one wave

// shared layout (float offsets)
constexpr int OFF_W1T = 0;                    // [120][64]
constexpr int OFF_W2T = OFF_W1T + 120 * 64;   // [64][64]
constexpr int OFF_W3T = OFF_W2T + 64 * 64;    // [64][64]
constexpr int OFF_W4  = OFF_W3T + 64 * 64;    // [3][64]
constexpr int OFF_B1  = OFF_W4 + 192;
constexpr int OFF_B2  = OFF_B1 + 64;
constexpr int OFF_B3  = OFF_B2 + 64;
constexpr int OFF_B4  = OFF_B3 + 64;          // 4
constexpr int OFF_F   = OFF_B4 + 4;           // feat [120][64]; stage; hB
constexpr int OFF_H   = OFF_F + 120 * 64;     // hA [64][64]
constexpr int SH_FLOATS = OFF_H + 64 * 64;    // 28036 floats = 112144 B
}

// ---- fp32x2 helpers -------------------------------------------------------
__device__ __forceinline__ unsigned long long pack2(float v) {
    unsigned long long r;
    asm("mov.b64 %0, {%1, %1};" : "=l"(r) : "f"(v));
    return r;
}
__device__ __forceinline__ float2 unpack2(unsigned long long v) {
    float2 r;
    asm("mov.b64 {%0, %1}, %2;" : "=f"(r.x), "=f"(r.y) : "l"(v));
    return r;
}
#define FMA2(acc, a, b) \
    asm("fma.rn.f32x2 %0, %1, %2, %0;" : "+l"(acc) : "l"(a), "l"(b))

// One MLP layer: warp computes outputs [obase, obase+8) for 64 cols; lane
// owns col pair (2*lane, 2*lane+1). actIn/actOut are [KDIM][64] smem.
template <int KDIM>
__device__ __forceinline__ void mlp_layer(const float* __restrict__ Wt,
                                          const float* __restrict__ bs,
                                          const float* __restrict__ actIn,
                                          float*       __restrict__ actOut,
                                          int obase, int lane) {
    unsigned long long accA[4], accB[4];
    {
        const ulonglong2* bp = reinterpret_cast<const ulonglong2*>(bs + obase);
        const ulonglong2 b0 = bp[0], b1 = bp[1];
        accA[0] = b0.x; accA[1] = b0.y; accA[2] = b1.x; accA[3] = b1.y;
        accB[0] = b0.x; accB[1] = b0.y; accB[2] = b1.x; accB[3] = b1.y;
    }
    const int rcol = 2 * lane;
    #pragma unroll 8
    for (int k = 0; k < KDIM; k++) {
        const float2 f =
            *reinterpret_cast<const float2*>(actIn + k * 64 + rcol);
        const unsigned long long fa = pack2(f.x);
        const unsigned long long fb = pack2(f.y);
        const ulonglong2* wp =
            reinterpret_cast<const ulonglong2*>(Wt + k * 64 + obase);
        const ulonglong2 w0 = wp[0], w1 = wp[1];
        FMA2(accA[0], fa, w0.x); FMA2(accB[0], fb, w0.x);
        FMA2(accA[1], fa, w0.y); FMA2(accB[1], fb, w0.y);
        FMA2(accA[2], fa, w1.x); FMA2(accB[2], fb, w1.x);
        FMA2(accA[3], fa, w1.y); FMA2(accB[3], fb, w1.y);
    }
    #pragma unroll
    for (int p = 0; p < 4; p++) {
        const float2 a = unpack2(accA[p]);
        const float2 b = unpack2(accB[p]);
        *reinterpret_cast<float2*>(actOut + (obase + 2 * p) * 64 + rcol) =
            make_float2(fmaxf(a.x, 0.0f), fmaxf(b.x, 0.0f));
        *reinterpret_cast<float2*>(actOut + (obase + 2 * p + 1) * 64 + rcol) =
            make_float2(fmaxf(a.y, 0.0f), fmaxf(b.y, 0.0f));
    }
}

__global__ __launch_bounds__(THREADS, 2)
void rgbnet_fused(const float* __restrict__ x,        // [N,4]
                  const int*   __restrict__ ifirst,   // [N]
                  const float* __restrict__ emb,      // [6,2^19,4]
                  const float* __restrict__ W1, const float* __restrict__ b1,
                  const float* __restrict__ W2, const float* __restrict__ b2,
                  const float* __restrict__ W3, const float* __restrict__ b3,
                  const float* __restrict__ W4, const float* __restrict__ b4,
                  float* __restrict__ out)             // [N,3]
{
    extern __shared__ float sh[];
    const int tid = threadIdx.x;
    float* stage = sh + OFF_F;   // 7744 floats max, spans F + head of H

    // ================= Phase W: weight transpose via padded staging ========
    // W1 [64][120] -> W1t [120][64]; stage padded stride 121 (odd, no conflicts)
    for (int i = tid; i < 7680; i += THREADS)
        stage[(i / 120) * 121 + (i % 120)] = __ldg(W1 + i);
    if (tid < 192) sh[OFF_W4 + tid] = __ldg(W4 + tid);
    if (tid < 64) {
        sh[OFF_B1 + tid] = __ldg(b1 + tid);
        sh[OFF_B2 + tid] = __ldg(b2 + tid);
        sh[OFF_B3 + tid] = __ldg(b3 + tid);
    }
    if (tid < 4) sh[OFF_B4 + tid] = (tid < 3) ? __ldg(b4 + tid) : 0.0f;
    __syncthreads();
    for (int i = tid; i < 7680; i += THREADS) {
        const int k = i >> 6, o = i & 63;
        sh[OFF_W1T + i] = stage[o * 121 + k];
    }
    __syncthreads();

    // W2 [64][64] -> W2t; stage stride 65
    for (int i = tid; i < 4096; i += THREADS)
        stage[(i >> 6) * 65 + (i & 63)] = __ldg(W2 + i);
    __syncthreads();
    for (int i = tid; i < 4096; i += THREADS) {
        const int k = i >> 6, o = i & 63;
        sh[OFF_W2T + i] = stage[o * 65 + k];
    }
    __syncthreads();

    // W3 [64][64] -> W3t
    for (int i = tid; i < 4096; i += THREADS)
        stage[(i >> 6) * 65 + (i & 63)] = __ldg(W3 + i);
    __syncthreads();
    for (int i = tid; i < 4096; i += THREADS) {
        const int k = i >> 6, o = i & 63;
        sh[OFF_W3T + i] = stage[o * 65 + k];
    }
    __syncthreads();

    // ================= Phase E: encode -> feat smem [120][64] ===============
    const int ray0 = blockIdx.x * RPB;
    float* feat = sh + OFF_F;

    for (int t = tid; t < 6 * 64; t += THREADS) {
        const int l   = t >> 6;            // warp-uniform level
        const int col = t & 63;
        int ray = ray0 + col;
        ray = ray < NRAYS - 1 ? ray : NRAYS - 1;

        const float4 xr  = __ldg(reinterpret_cast<const float4*>(x) + ray);
        const int    if0 = __ldg(ifirst + ray);

        const int   R   = 4 << l;
        const float fR  = (float)R;
        const int   Rp1 = R + 1;
        const float4* __restrict__ tab =
            reinterpret_cast<const float4*>(emb) + (size_t)l * HSIZE;

        int    prev_key = -1;
        float4 cc[8];

        #pragma unroll
        for (int s = 0; s < 5; s++) {
            int sc = if0 + s - 2;
            sc = sc < 0 ? 0 : (sc > NSAMP - 1 ? NSAMP - 1 : sc);
            const float tt  = (float)sc * (1.0f / 299.0f);
            const float omt = 1.0f - tt;
            const float px = xr.x * omt + xr.z * tt;
            const float py = xr.y * omt + xr.w * tt;
            const float pz = tt;

            const float fx = px * fR, fy = py * fR, fz = pz * fR;
            const float flx = floorf(fx), fly = floorf(fy), flz = floorf(fz);
            const int ix = (int)flx, iy = (int)fly, iz = (int)flz;
            const float wx = fx - flx, wy = fy - fly, wz = fz - flz;

            const int key = ix | (iy << 10) | (iz << 20);
            if (key != prev_key) {
                prev_key = key;
                #pragma unroll
                for (int c = 0; c < 8; c++) {
                    const int bx = (c >> 2) & 1, by = (c >> 1) & 1, bz = c & 1;
                    int cx = ix + bx; cx = cx > R ? R : cx;
                    int cy = iy + by; cy = cy > R ? R : cy;
                    int cz = iz + bz; cz = cz > R ? R : cz;
                    const unsigned id_dense =
                        (unsigned)(cx + cy * Rp1 + cz * Rp1 * Rp1);
                    const unsigned id_hash =
                        ((unsigned)cx ^ ((unsigned)cy * 2654435761u)
                                     ^ ((unsigned)cz * 805459861u)) & HMASK;
                    const unsigned idx = (l == 5) ? id_hash : id_dense;
                    cc[c] = __ldg(tab + idx);
                }
            }

            float ax = 0.f, ay = 0.f, az = 0.f, aw = 0.f;
            #pragma unroll
            for (int c = 0; c < 8; c++) {
                const int bx = (c >> 2) & 1, by = (c >> 1) & 1, bz = c & 1;
                const float wgt = (bx ? wx : 1.0f - wx)
                                * (by ? wy : 1.0f - wy)
                                * (bz ? wz : 1.0f - wz);
                ax = fmaf(wgt, cc[c].x, ax);
                ay = fmaf(wgt, cc[c].y, ay);
                az = fmaf(wgt, cc[c].z, az);
                aw = fmaf(wgt, cc[c].w, aw);
            }

            const int kb = (s * 6 + l) * 4;
            feat[(kb + 0) * 64 + col] = ax;
            feat[(kb + 1) * 64 + col] = ay;
            feat[(kb + 2) * 64 + col] = az;
            feat[(kb + 3) * 64 + col] = aw;
        }
    }
    __syncthreads();

    // ================= Phase M: MLP =========================================
    const int lane  = tid & 31;
    const int warp  = tid >> 5;            // 0..7
    const int obase = warp * 8;
    float* F = sh + OFF_F;                 // feat, then hB
    float* H = sh + OFF_H;                 // hA

    mlp_layer<120>(sh + OFF_W1T, sh + OFF_B1, F, H, obase, lane);  // feat->hA
    __syncthreads();
    mlp_layer<64 >(sh + OFF_W2T, sh + OFF_B2, H, F, obase, lane);  // hA->hB
    __syncthreads();
    mlp_layer<64 >(sh + OFF_W3T, sh + OFF_B3, F, H, obase, lane);  // hB->hA
    __syncthreads();

    // layer 4: 64 -> 3, one thread per valid ray
    if (tid < RPB) {
        const int ray = ray0 + tid;
        if (ray < NRAYS) {
            const float* W4s = sh + OFF_W4;
            float a0 = sh[OFF_B4 + 0], a1 = sh[OFF_B4 + 1], a2 = sh[OFF_B4 + 2];
            #pragma unroll 8
            for (int k = 0; k < 64; k++) {
                const float hv = H[k * 64 + tid];
                a0 = fmaf(hv, W4s[k],       a0);
                a1 = fmaf(hv, W4s[64 + k],  a1);
                a2 = fmaf(hv, W4s[128 + k], a2);
            }
            float* o = out + (size_t)ray * 3;
            o[0] = a0; o[1] = a1; o[2] = a2;
        }
    }
}

extern "C" void kernel_launch(void* const* d_in, const int* in_sizes, int n_in,
                              void* d_out, int out_size) {
    const float* x    = (const float*)d_in[0];
    const int*   idxf = (const int*)  d_in[1];
    const float* emb  = (const float*)d_in[2];
    const float* W1   = (const float*)d_in[3];
    const float* b1   = (const float*)d_in[4];
    const float* W2   = (const float*)d_in[5];
    const float* b2   = (const float*)d_in[6];
    const float* W3   = (const float*)d_in[7];
    const float* b3   = (const float*)d_in[8];
    const float* W4   = (const float*)d_in[9];
    const float* b4   = (const float*)d_in[10];
    float* out = (float*)d_out;

    const size_t shbytes = (size_t)SH_FLOATS * sizeof(float);   // 112144 B
    cudaFuncSetAttribute(rgbnet_fused,
                         cudaFuncAttributeMaxDynamicSharedMemorySize,
                         (int)shbytes);
    rgbnet_fused<<<BLOCKS, THREADS, shbytes>>>(
        x, idxf, emb, W1, b1, W2, b2, W3, b3, W4, b4, out);
}

// round 8
// speedup vs baseline: 1.2810x; 1.2810x over previous
#include <cuda_runtime.h>

// ---------------------------------------------------------------------------
// RgbNet, R8: R6 two-kernel structure, K2 gains k-split warp pairs.
//  K1 encode: thread per (ray, level), 5 samples w/ register corner cache;
//             weight transpose piggybacked. Writes g_feat[120][16384].
//  K2 mlp:    512 thr / 16 warps / 64 rays per block; warp = 8 outputs x
//             64 rays x HALF the k range. Warp pair (w, w+8) shares an
//             output chunk: k-hi warp stores raw partials into the dest
//             h-buffer, k-lo warp adds its half + bias, relu, final store.
//             4096 warps total (~28/SM) at R6's aux-instruction ratio.
// ---------------------------------------------------------------------------

namespace {
constexpr int NRAYS   = 16384;
constexpr int NSAMP   = 300;
constexpr unsigned HSIZE = 1u << 19;
constexpr unsigned HMASK = HSIZE - 1u;
constexpr int WSTAGE  = 120 * 64 + 64 * 64 + 64 * 64;   // 15872 floats

constexpr int ENC_THREADS = 256;
constexpr int ENC_TASKS   = NRAYS * 6;
constexpr int ENC_BLOCKS  = ENC_TASKS / ENC_THREADS;     // 384

constexpr int MLP_THREADS = 512;     // 16 warps
constexpr int MLP_RPB     = 64;      // rays per block
constexpr int MLP_BLOCKS  = NRAYS / MLP_RPB;             // 256

// K2 shared layout (float offsets)
constexpr int OFF_W1T = 0;                    // [120][64]
constexpr int OFF_W2T = OFF_W1T + 120 * 64;   // [64][64]
constexpr int OFF_W3T = OFF_W2T + 64 * 64;    // [64][64]
constexpr int OFF_W4  = OFF_W3T + 64 * 64;    // [3][64]
constexpr int OFF_B1  = OFF_W4 + 192;
constexpr int OFF_B2  = OFF_B1 + 64;
constexpr int OFF_B3  = OFF_B2 + 64;
constexpr int OFF_B4  = OFF_B3 + 64;          // 4
constexpr int OFF_HA  = OFF_B4 + 4;           // [64][64]
constexpr int OFF_HB  = OFF_HA + 64 * 64;     // [64][64]
constexpr int SH_FLOATS = OFF_HB + 64 * 64;   // 24452 floats = 97808 B
}

__device__ float g_Wt[WSTAGE];            // [W1t | W2t | W3t], each [k][o]
__device__ float g_feat[120 * NRAYS];     // [k][ray]

// ---- fp32x2 helpers -------------------------------------------------------
__device__ __forceinline__ unsigned long long pack2(float v) {
    unsigned long long r;
    asm("mov.b64 %0, {%1, %1};" : "=l"(r) : "f"(v));
    return r;
}
__device__ __forceinline__ float2 unpack2(unsigned long long v) {
    float2 r;
    asm("mov.b64 {%0, %1}, %2;" : "=f"(r.x), "=f"(r.y) : "l"(v));
    return r;
}
#define FMA2(acc, a, b) \
    asm("fma.rn.f32x2 %0, %1, %2, %0;" : "+l"(acc) : "l"(a), "l"(b))

// ===========================================================================
// Kernel 1: encoding, thread per (ray, level), 5 samples with corner cache
// ===========================================================================
__global__ __launch_bounds__(ENC_THREADS)
void encode_kernel(const float* __restrict__ x,       // [N,4]
                   const int*   __restrict__ ifirst,  // [N]
                   const float* __restrict__ emb,     // [6,2^19,4]
                   const float* __restrict__ W1,
                   const float* __restrict__ W2,
                   const float* __restrict__ W3)
{
    const int t = blockIdx.x * ENC_THREADS + threadIdx.x;

    if (t < WSTAGE) {
        float v;
        if (t < 7680) {
            int k = t >> 6, o = t & 63;
            v = W1[o * 120 + k];
        } else if (t < 11776) {
            int j = t - 7680; int k = j >> 6, o = j & 63;
            v = W2[o * 64 + k];
        } else {
            int j = t - 11776; int k = j >> 6, o = j & 63;
            v = W3[o * 64 + k];
        }
        g_Wt[t] = v;
    }

    const int ray = t & (NRAYS - 1);
    const int l   = t >> 14;                 // 0..5, uniform per warp

    const float4 xr  = __ldg(reinterpret_cast<const float4*>(x) + ray);
    const int    if0 = __ldg(ifirst + ray);

    const int   R   = 4 << l;
    const float fR  = (float)R;
    const int   Rp1 = R + 1;
    const float4* __restrict__ tab =
        reinterpret_cast<const float4*>(emb) + (size_t)l * HSIZE;

    int    prev_key = -1;
    float4 cc[8];

    #pragma unroll
    for (int s = 0; s < 5; s++) {
        int sc = if0 + s - 2;
        sc = sc < 0 ? 0 : (sc > NSAMP - 1 ? NSAMP - 1 : sc);
        const float tt  = (float)sc * (1.0f / 299.0f);
        const float omt = 1.0f - tt;
        const float px = xr.x * omt + xr.z * tt;
        const float py = xr.y * omt + xr.w * tt;
        const float pz = tt;

        const float fx = px * fR, fy = py * fR, fz = pz * fR;
        const float flx = floorf(fx), fly = floorf(fy), flz = floorf(fz);
        const int ix = (int)flx, iy = (int)fly, iz = (int)flz;
        const float wx = fx - flx, wy = fy - fly, wz = fz - flz;

        const int key = ix | (iy << 10) | (iz << 20);
        if (key != prev_key) {
            prev_key = key;
            #pragma unroll
            for (int c = 0; c < 8; c++) {
                const int bx = (c >> 2) & 1, by = (c >> 1) & 1, bz = c & 1;
                int cx = ix + bx; cx = cx > R ? R : cx;
                int cy = iy + by; cy = cy > R ? R : cy;
                int cz = iz + bz; cz = cz > R ? R : cz;
                const unsigned id_dense =
                    (unsigned)(cx + cy * Rp1 + cz * Rp1 * Rp1);
                const unsigned id_hash =
                    ((unsigned)cx ^ ((unsigned)cy * 2654435761u)
                                 ^ ((unsigned)cz * 805459861u)) & HMASK;
                const unsigned idx = (l == 5) ? id_hash : id_dense;
                cc[c] = __ldg(tab + idx);
            }
        }

        float ax = 0.f, ay = 0.f, az = 0.f, aw = 0.f;
        #pragma unroll
        for (int c = 0; c < 8; c++) {
            const int bx = (c >> 2) & 1, by = (c >> 1) & 1, bz = c & 1;
            const float wgt = (bx ? wx : 1.0f - wx)
                            * (by ? wy : 1.0f - wy)
                            * (bz ? wz : 1.0f - wz);
            ax = fmaf(wgt, cc[c].x, ax);
            ay = fmaf(wgt, cc[c].y, ay);
            az = fmaf(wgt, cc[c].z, az);
            aw = fmaf(wgt, cc[c].w, aw);
        }

        const int kb = (s * 6 + l) * 4;
        g_feat[(size_t)(kb + 0) * NRAYS + ray] = ax;
        g_feat[(size_t)(kb + 1) * NRAYS + ray] = ay;
        g_feat[(size_t)(kb + 2) * NRAYS + ray] = az;
        g_feat[(size_t)(kb + 3) * NRAYS + ray] = aw;
    }
}

// ===========================================================================
// Kernel 2: MLP, k-split warp pairs.
// ===========================================================================

// Combine partials / store. khalf==1: raw partial store. khalf==0: add
// partial read from actOut, add bias-side acc, relu, final store.
__device__ __forceinline__ void finish_layer(unsigned long long* accA,
                                             unsigned long long* accB,
                                             float* __restrict__ actOut,
                                             int obase, int rcol, int khalf) {
    if (khalf == 1) {
        #pragma unroll
        for (int p = 0; p < 4; p++) {
            const float2 a = unpack2(accA[p]);
            const float2 b = unpack2(accB[p]);
            *reinterpret_cast<float2*>(actOut + (obase + 2 * p) * 64 + rcol) =
                make_float2(a.x, b.x);
            *reinterpret_cast<float2*>(actOut + (obase + 2 * p + 1) * 64 + rcol) =
                make_float2(a.y, b.y);
        }
    }
    __syncthreads();
    if (khalf == 0) {
        #pragma unroll
        for (int p = 0; p < 4; p++) {
            const float2 p0 = *reinterpret_cast<const float2*>(
                actOut + (obase + 2 * p) * 64 + rcol);
            const float2 p1 = *reinterpret_cast<const float2*>(
                actOut + (obase + 2 * p + 1) * 64 + rcol);
            const float2 a = unpack2(accA[p]);
            const float2 b = unpack2(accB[p]);
            *reinterpret_cast<float2*>(actOut + (obase + 2 * p) * 64 + rcol) =
                make_float2(fmaxf(a.x + p0.x, 0.0f), fmaxf(b.x + p0.y, 0.0f));
            *reinterpret_cast<float2*>(actOut + (obase + 2 * p + 1) * 64 + rcol) =
                make_float2(fmaxf(a.y + p1.x, 0.0f), fmaxf(b.y + p1.y, 0.0f));
        }
    }
    __syncthreads();
}

// Hidden layer 64->64, k-split: this warp covers k in [khalf*32, khalf*32+32)
__device__ __forceinline__ void layer_hidden_ks(const float* __restrict__ Wt,
                                                const float* __restrict__ bs,
                                                const float* __restrict__ actIn,
                                                float*       __restrict__ actOut,
                                                int obase, int lane, int khalf) {
    unsigned long long accA[4], accB[4];
    if (khalf == 0) {
        const ulonglong2* bp = reinterpret_cast<const ulonglong2*>(bs + obase);
        const ulonglong2 b0 = bp[0], b1 = bp[1];
        accA[0] = b0.x; accA[1] = b0.y; accA[2] = b1.x; accA[3] = b1.y;
        accB[0] = b0.x; accB[1] = b0.y; accB[2] = b1.x; accB[3] = b1.y;
    } else {
        #pragma unroll
        for (int p = 0; p < 4; p++) { accA[p] = 0ull; accB[p] = 0ull; }
    }
    const int rcol = 2 * lane;
    const int k0 = khalf * 32;
    #pragma unroll 8
    for (int kk = 0; kk < 32; kk++) {
        const int k = k0 + kk;
        const float2 f =
            *reinterpret_cast<const float2*>(actIn + k * 64 + rcol);
        const unsigned long long fa = pack2(f.x);
        const unsigned long long fb = pack2(f.y);
        const ulonglong2* wp =
            reinterpret_cast<const ulonglong2*>(Wt + k * 64 + obase);
        const ulonglong2 w0 = wp[0], w1 = wp[1];
        FMA2(accA[0], fa, w0.x); FMA2(accB[0], fb, w0.x);
        FMA2(accA[1], fa, w0.y); FMA2(accB[1], fb, w0.y);
        FMA2(accA[2], fa, w1.x); FMA2(accB[2], fb, w1.x);
        FMA2(accA[3], fa, w1.y); FMA2(accB[3], fb, w1.y);
    }
    finish_layer(accA, accB, actOut, obase, rcol, khalf);
}

__global__ __launch_bounds__(MLP_THREADS, 2)
void mlp_kernel(const float* __restrict__ b1, const float* __restrict__ b2,
                const float* __restrict__ b3,
                const float* __restrict__ W4, const float* __restrict__ b4,
                float* __restrict__ out)
{
    extern __shared__ float sh[];
    const int tid = threadIdx.x;

    // ---- stage pre-transposed weights (coalesced float4) -------------------
    {
        const float4* src = reinterpret_cast<const float4*>(g_Wt);
        float4*       dst = reinterpret_cast<float4*>(sh);
        #pragma unroll
        for (int i = tid; i < WSTAGE / 4; i += MLP_THREADS) dst[i] = src[i];
    }
    if (tid < 192) sh[OFF_W4 + tid] = __ldg(W4 + tid);
    if (tid < 64) {
        sh[OFF_B1 + tid] = __ldg(b1 + tid);
        sh[OFF_B2 + tid] = __ldg(b2 + tid);
        sh[OFF_B3 + tid] = __ldg(b3 + tid);
    }
    if (tid < 4) sh[OFF_B4 + tid] = (tid < 3) ? __ldg(b4 + tid) : 0.0f;
    __syncthreads();

    const int lane  = tid & 31;
    const int warp  = tid >> 5;                 // 0..15
    const int khalf = warp >> 3;                // 0 = k-lo (+bias), 1 = k-hi
    const int obase = (warp & 7) * 8;           // 8-output chunk
    const int rcol  = 2 * lane;                 // ray pair within block
    const int ray0  = blockIdx.x * MLP_RPB + rcol;

    float* hA = sh + OFF_HA;
    float* hB = sh + OFF_HB;

    // ---------------- layer 1: 120 -> 64, feats from g_feat -----------------
    // k-lo warp: k in [0,60); k-hi warp: k in [60,120).
    {
        unsigned long long accA[4], accB[4];
        if (khalf == 0) {
            const ulonglong2* bp =
                reinterpret_cast<const ulonglong2*>(sh + OFF_B1 + obase);
            const ulonglong2 b0 = bp[0], bb1 = bp[1];
            accA[0] = b0.x; accA[1] = b0.y; accA[2] = bb1.x; accA[3] = bb1.y;
            accB[0] = b0.x; accB[1] = b0.y; accB[2] = bb1.x; accB[3] = bb1.y;
        } else {
            #pragma unroll
            for (int p = 0; p < 4; p++) { accA[p] = 0ull; accB[p] = 0ull; }
        }
        const float* __restrict__ Wt = sh + OFF_W1T;
        const int k0 = khalf * 60;

        float2 fbuf[4];
        #pragma unroll
        for (int j = 0; j < 4; j++)
            fbuf[j] = __ldg(reinterpret_cast<const float2*>(
                          &g_feat[(size_t)(k0 + j) * NRAYS + ray0]));

        for (int kb = 0; kb < 60; kb += 4) {
            float2 fc[4];
            #pragma unroll
            for (int j = 0; j < 4; j++) fc[j] = fbuf[j];
            if (kb + 4 < 60) {
                #pragma unroll
                for (int j = 0; j < 4; j++)
                    fbuf[j] = __ldg(reinterpret_cast<const float2*>(
                        &g_feat[(size_t)(k0 + kb + 4 + j) * NRAYS + ray0]));
            }
            #pragma unroll
            for (int j = 0; j < 4; j++) {
                const unsigned long long fa = pack2(fc[j].x);
                const unsigned long long fb = pack2(fc[j].y);
                const ulonglong2* wp = reinterpret_cast<const ulonglong2*>(
                    Wt + (k0 + kb + j) * 64 + obase);
                const ulonglong2 w0 = wp[0], w1 = wp[1];
                FMA2(accA[0], fa, w0.x); FMA2(accB[0], fb, w0.x);
                FMA2(accA[1], fa, w0.y); FMA2(accB[1], fb, w0.y);
                FMA2(accA[2], fa, w1.x); FMA2(accB[2], fb, w1.x);
                FMA2(accA[3], fa, w1.y); FMA2(accB[3], fb, w1.y);
            }
        }
        finish_layer(accA, accB, hA, obase, rcol, khalf);
    }

    // ---------------- layer 2: hA -> hB --------------------------------------
    layer_hidden_ks(sh + OFF_W2T, sh + OFF_B2, hA, hB, obase, lane, khalf);

    // ---------------- layer 3: hB -> hA --------------------------------------
    layer_hidden_ks(sh + OFF_W3T, sh + OFF_B3, hB, hA, obase, lane, khalf);

    // ---------------- layer 4: 64 -> 3, threads 0..63 ------------------------
    if (tid < MLP_RPB) {
        const float* W4s = sh + OFF_W4;
        float a0 = sh[OFF_B4 + 0], a1 = sh[OFF_B4 + 1], a2 = sh[OFF_B4 + 2];
        #pragma unroll 8
        for (int k = 0; k < 64; k++) {
            const float hv = hA[k * 64 + tid];
            a0 = fmaf(hv, W4s[k],       a0);
            a1 = fmaf(hv, W4s[64 + k],  a1);
            a2 = fmaf(hv, W4s[128 + k], a2);
        }
        float* o = out + (size_t)(blockIdx.x * MLP_RPB + tid) * 3;
        o[0] = a0; o[1] = a1; o[2] = a2;
    }
}

extern "C" void kernel_launch(void* const* d_in, const int* in_sizes, int n_in,
                              void* d_out, int out_size) {
    const float* x    = (const float*)d_in[0];
    const int*   idxf = (const int*)  d_in[1];
    const float* emb  = (const float*)d_in[2];
    const float* W1   = (const float*)d_in[3];
    const float* b1   = (const float*)d_in[4];
    const float* W2   = (const float*)d_in[5];
    const float* b2   = (const float*)d_in[6];
    const float* W3   = (const float*)d_in[7];
    const float* b3   = (const float*)d_in[8];
    const float* W4   = (const float*)d_in[9];
    const float* b4   = (const float*)d_in[10];
    float* out = (float*)d_out;

    encode_kernel<<<ENC_BLOCKS, ENC_THREADS>>>(x, idxf, emb, W1, W2, W3);

    const size_t shbytes = (size_t)SH_FLOATS * sizeof(float);   // 97808 B
    cudaFuncSetAttribute(mlp_kernel,
                         cudaFuncAttributeMaxDynamicSharedMemorySize,
                         (int)shbytes);
    mlp_kernel<<<MLP_BLOCKS, MLP_THREADS, shbytes>>>(b1, b2, b3, W4, b4, out);
}